// round 1
// baseline (speedup 1.0000x reference)
#include <cuda_runtime.h>

// Correlation / cost-volume layer: kernel_size=1, stride=1, max_disp=4.
// out[b, d, y, x] = (1/C) * sum_c in1[b,c,y,x] * in2[b,c, y+dy-4, x+dx-4]
// with d = dy*9 + dx, dy,dx in [0,9), zero padding outside.
//
// Shapes fixed by the reference: B=8, C=192, H=W=128, 81 displacements.

#define MAXD 4
#define WIN  9
#define NDISP 81

#define BB 8
#define CC 192
#define HH 128
#define WW 128

#define TH 8          // tile rows per CTA
#define TW 32         // tile cols per CTA
#define KC 12         // channels per chunk (192 / 12 = 16 chunks)
#define NTHREADS 192  // 3 dy-groups * (8 ty * 8 tx)

__global__ __launch_bounds__(NTHREADS, 2)
void corr_kernel(const float* __restrict__ in1,
                 const float* __restrict__ in2,
                 float* __restrict__ out)
{
    __shared__ float s1[KC][TH][TW];              // 12*8*32*4  = 12 KB
    __shared__ float s2[KC][TH + 8][TW + 8];      // 12*16*40*4 = 30 KB

    const int tx0 = blockIdx.x * TW;   // 0..96
    const int ty0 = blockIdx.y * TH;   // 0..120
    const int b   = blockIdx.z;        // 0..7

    const int tid   = threadIdx.x;
    const int group = tid / 64;        // dy group: handles dy in [group*3, group*3+3)
    const int ptid  = tid % 64;
    const int tx    = ptid % 8;        // x position / 4
    const int ty    = ptid / 8;        // 0..7
    const int dyb   = group * 3;

    float acc[3][WIN][4];
    #pragma unroll
    for (int g = 0; g < 3; ++g)
        #pragma unroll
        for (int dx = 0; dx < WIN; ++dx)
            #pragma unroll
            for (int px = 0; px < 4; ++px)
                acc[g][dx][px] = 0.0f;

    for (int c0 = 0; c0 < CC; c0 += KC) {
        // ---- stage in1 tile: KC x TH x TW, fully in bounds, coalesced ----
        #pragma unroll
        for (int i = tid; i < KC * TH * TW; i += NTHREADS) {
            int kc  = i / (TH * TW);
            int rem = i % (TH * TW);
            int r   = rem / TW;
            int col = rem % TW;
            s1[kc][r][col] =
                in1[(((b * CC) + c0 + kc) * HH + (ty0 + r)) * WW + (tx0 + col)];
        }
        // ---- stage in2 halo tile: KC x (TH+8) x (TW+8), zero-pad OOB ----
        #pragma unroll
        for (int i = tid; i < KC * (TH + 8) * (TW + 8); i += NTHREADS) {
            int kc  = i / ((TH + 8) * (TW + 8));
            int rem = i % ((TH + 8) * (TW + 8));
            int r   = rem / (TW + 8);
            int col = rem % (TW + 8);
            int gy = ty0 + r - MAXD;
            int gx = tx0 + col - MAXD;
            float v = 0.0f;
            if (gy >= 0 && gy < HH && gx >= 0 && gx < WW)
                v = in2[(((b * CC) + c0 + kc) * HH + gy) * WW + gx];
            s2[kc][r][col] = v;
        }
        __syncthreads();

        // ---- compute: per channel, 1 in1 float4 + 3x (12-wide in2 window) ----
        #pragma unroll 4
        for (int kc = 0; kc < KC; ++kc) {
            float4 a4 = *(const float4*)&s1[kc][ty][tx * 4];
            float a[4] = {a4.x, a4.y, a4.z, a4.w};
            #pragma unroll
            for (int g = 0; g < 3; ++g) {
                const float* row = &s2[kc][ty + dyb + g][tx * 4];
                float4 r0 = *(const float4*)(row);
                float4 r1 = *(const float4*)(row + 4);
                float4 r2 = *(const float4*)(row + 8);
                float r[12] = {r0.x, r0.y, r0.z, r0.w,
                               r1.x, r1.y, r1.z, r1.w,
                               r2.x, r2.y, r2.z, r2.w};
                #pragma unroll
                for (int dx = 0; dx < WIN; ++dx) {
                    #pragma unroll
                    for (int px = 0; px < 4; ++px)
                        acc[g][dx][px] = fmaf(a[px], r[dx + px], acc[g][dx][px]);
                }
            }
        }
        __syncthreads();
    }

    // ---- epilogue: scale by 1/C, float4 stores, fully coalesced ----
    const float scale = 1.0f / (float)CC;
    const int y  = ty0 + ty;
    const int x0 = tx0 + tx * 4;
    #pragma unroll
    for (int g = 0; g < 3; ++g) {
        #pragma unroll
        for (int dx = 0; dx < WIN; ++dx) {
            int d = (dyb + g) * WIN + dx;
            float4 v = make_float4(acc[g][dx][0] * scale,
                                   acc[g][dx][1] * scale,
                                   acc[g][dx][2] * scale,
                                   acc[g][dx][3] * scale);
            *(float4*)&out[(((b * NDISP) + d) * HH + y) * WW + x0] = v;
        }
    }
}

extern "C" void kernel_launch(void* const* d_in, const int* in_sizes, int n_in,
                              void* d_out, int out_size)
{
    const float* in1 = (const float*)d_in[0];
    const float* in2 = (const float*)d_in[1];
    float* out = (float*)d_out;

    dim3 grid(WW / TW, HH / TH, BB);   // (4, 16, 8) = 512 CTAs
    dim3 block(NTHREADS);
    corr_kernel<<<grid, block>>>(in1, in2, out);
}

// round 2
// speedup vs baseline: 2.5518x; 2.5518x over previous
#include <cuda_runtime.h>
#include <cuda_pipeline.h>

// Correlation / cost-volume layer: kernel_size=1, stride=1, max_disp=4.
// out[b, d, y, x] = (1/C) * sum_c in1[b,c,y,x] * in2[b,c, y+dy-4, x+dx-4]
// d = dy*9 + dx, dy,dx in [0,9), zero padding outside.
// Fixed shapes: B=8, C=192, H=W=128, 81 displacements.

#define MAXD 4
#define WIN  9
#define NDISP 81

#define BB 8
#define CC 192
#define HH 128
#define WW 128

#define TH 8           // tile rows per CTA
#define TW 32          // tile cols per CTA
#define KC 6           // channels per chunk (32 chunks)
#define NCHUNK (CC / KC)
#define NTHREADS 192   // 3 dy-groups * (8 ty * 8 tx)

#define S1SZ (KC * TH * TW)              // floats per s1 stage
#define S2H  (TH + 8)
#define S2W  (TW + 8)
#define S2SZ (KC * S2H * S2W)            // floats per s2 stage

__global__ __launch_bounds__(NTHREADS, 2)
void corr_kernel(const float* __restrict__ in1,
                 const float* __restrict__ in2,
                 float* __restrict__ out)
{
    __shared__ float s1[2][KC][TH][TW];          // 2*6*8*32*4  = 12 KB
    __shared__ float s2[2][KC][S2H][S2W];        // 2*6*16*40*4 = 30 KB

    const int tx0 = blockIdx.x * TW;
    const int ty0 = blockIdx.y * TH;
    const int b   = blockIdx.z;

    const int tid   = threadIdx.x;
    const int group = tid / 64;        // dy group
    const int ptid  = tid % 64;
    const int tx    = ptid % 8;        // x position / 4
    const int ty    = ptid / 8;
    const int dyb   = group * 3;

    float* const s1f = &s1[0][0][0][0];
    float* const s2f = &s2[0][0][0][0];

    // ---- chunk-invariant staging descriptors ----
    // s1: 384 16B-chunks per stage, 2 per thread
    const float* g1p[2];
    int s1off[2];
    #pragma unroll
    for (int t = 0; t < 2; ++t) {
        int idx = tid + t * NTHREADS;          // 0..383
        int kc  = idx >> 6;                    // /64
        int rem = idx & 63;
        int r   = rem >> 3;
        int c4  = rem & 7;
        s1off[t] = (kc * TH + r) * TW + c4 * 4;
        g1p[t]   = in1 + (((long)(b * CC + kc) * HH + (ty0 + r)) * WW + tx0 + c4 * 4);
    }
    // s2: 960 16B-chunks per stage, 5 per thread, chunk-invariant validity
    const float* g2p[5];
    int s2off[5];
    unsigned zfill[5];
    #pragma unroll
    for (int t = 0; t < 5; ++t) {
        int idx = tid + t * NTHREADS;          // 0..959
        int kc  = idx / 160;
        int rem = idx % 160;
        int r   = rem / 10;
        int c   = rem % 10;
        int gy  = ty0 + r - MAXD;
        int gx  = tx0 + c * 4 - MAXD;
        bool valid = (gy >= 0) && (gy < HH) && (gx >= 0) && (gx <= WW - 4);
        zfill[t] = valid ? 0u : 16u;
        int cgy = min(max(gy, 0), HH - 1);
        int cgx = min(max(gx, 0), WW - 4);
        s2off[t] = (kc * S2H + r) * S2W + c;   // c in units of 4 floats handled below
        s2off[t] = (kc * S2H + r) * S2W + c * 4;
        g2p[t]   = in2 + (((long)(b * CC + kc) * HH + cgy) * WW + cgx);
    }

    // ---- accumulators ----
    float acc[3][WIN][4];
    #pragma unroll
    for (int g = 0; g < 3; ++g)
        #pragma unroll
        for (int dx = 0; dx < WIN; ++dx)
            #pragma unroll
            for (int px = 0; px < 4; ++px)
                acc[g][dx][px] = 0.0f;

    const long CHUNK_STRIDE = (long)KC * HH * WW;

    // prologue: stage chunk 0 into buf 0
    #pragma unroll
    for (int t = 0; t < 2; ++t)
        __pipeline_memcpy_async(s1f + s1off[t], g1p[t], 16);
    #pragma unroll
    for (int t = 0; t < 5; ++t)
        __pipeline_memcpy_async(s2f + s2off[t], g2p[t], 16, zfill[t]);
    __pipeline_commit();

    #pragma unroll 2
    for (int k = 0; k < NCHUNK; ++k) {
        const int buf = k & 1;
        if (k + 1 < NCHUNK) {
            const long coff = (long)(k + 1) * CHUNK_STRIDE;
            const int nb = (buf ^ 1);
            #pragma unroll
            for (int t = 0; t < 2; ++t)
                __pipeline_memcpy_async(s1f + nb * S1SZ + s1off[t], g1p[t] + coff, 16);
            #pragma unroll
            for (int t = 0; t < 5; ++t)
                __pipeline_memcpy_async(s2f + nb * S2SZ + s2off[t], g2p[t] + coff, 16, zfill[t]);
            __pipeline_commit();
            __pipeline_wait_prior(1);
        } else {
            __pipeline_wait_prior(0);
        }
        __syncthreads();

        // ---- compute chunk k from buf ----
        #pragma unroll
        for (int kc = 0; kc < KC; ++kc) {
            float4 a4 = *(const float4*)&s1[buf][kc][ty][tx * 4];
            float a[4] = {a4.x, a4.y, a4.z, a4.w};
            #pragma unroll
            for (int g = 0; g < 3; ++g) {
                const float* row = &s2[buf][kc][ty + dyb + g][tx * 4];
                float4 r0 = *(const float4*)(row);
                float4 r1 = *(const float4*)(row + 4);
                float4 r2 = *(const float4*)(row + 8);
                float r[12] = {r0.x, r0.y, r0.z, r0.w,
                               r1.x, r1.y, r1.z, r1.w,
                               r2.x, r2.y, r2.z, r2.w};
                #pragma unroll
                for (int dx = 0; dx < WIN; ++dx) {
                    #pragma unroll
                    for (int px = 0; px < 4; ++px)
                        acc[g][dx][px] = fmaf(a[px], r[dx + px], acc[g][dx][px]);
                }
            }
        }
        __syncthreads();
    }

    // ---- epilogue: scale by 1/C, float4 stores, coalesced ----
    const float scale = 1.0f / (float)CC;
    const int y  = ty0 + ty;
    const int x0 = tx0 + tx * 4;
    #pragma unroll
    for (int g = 0; g < 3; ++g) {
        #pragma unroll
        for (int dx = 0; dx < WIN; ++dx) {
            int d = (dyb + g) * WIN + dx;
            float4 v = make_float4(acc[g][dx][0] * scale,
                                   acc[g][dx][1] * scale,
                                   acc[g][dx][2] * scale,
                                   acc[g][dx][3] * scale);
            *(float4*)&out[(((long)(b * NDISP) + d) * HH + y) * WW + x0] = v;
        }
    }
}

extern "C" void kernel_launch(void* const* d_in, const int* in_sizes, int n_in,
                              void* d_out, int out_size)
{
    const float* in1 = (const float*)d_in[0];
    const float* in2 = (const float*)d_in[1];
    float* out = (float*)d_out;

    dim3 grid(WW / TW, HH / TH, BB);   // (4, 16, 8) = 512 CTAs
    dim3 block(NTHREADS);
    corr_kernel<<<grid, block>>>(in1, in2, out);
}